// round 1
// baseline (speedup 1.0000x reference)
#include <cuda_runtime.h>
#include <math.h>

#define H_ 200
#define W_ 352
#define HW_ (H_*W_)
#define CHW_ (64*HW_)

typedef unsigned long long ull;

// ---------------- scratch (static device memory; no allocations) ----------------
__device__ __align__(16) float g_agg[4*CHW_];   // agg = 0.5*(x0+message), per batch
__device__ __align__(16) float g_h  [CHW_];     // GRU hidden state
__device__ __align__(16) float g_rh [CHW_];     // reset * h
__device__ __align__(16) float g_u  [CHW_];     // update gate
// packed weights: for each ci, 32 channel-pairs x 9 taps as float2 (= 144 float4)
__device__ float4 g_wmsg  [128*144];
__device__ float4 g_wgates[2*192*144];
__device__ float4 g_wcan  [192*144];

// ---------------- helpers ----------------
__device__ __forceinline__ ull pk2(float a, float b) {
    ull r; asm("mov.b64 %0,{%1,%2};" : "=l"(r) : "f"(a), "f"(b)); return r;
}
__device__ __forceinline__ void fma2(ull& d, ull a, ull b) {
    asm("fma.rn.f32x2 %0,%1,%2,%0;" : "+l"(d) : "l"(a), "l"(b));
}

struct SB {
    float4 in4[6][10];   // 6 input rows x 40 cols (halo'd, float4-staged)
    float4 w4[144];      // 32 pairs x 9 taps as float2 pairs
};

enum { MODE_MSG = 0, MODE_GATES = 1, MODE_CAN = 2 };

// ---------------- fused conv3x3 + epilogue ----------------
// Tile: 32 (W, lanes) x 4 (H, per-thread rows) pixels, 64 out channels
// (8 warps x 8 channels = 4 fp32x2 channel-pairs per warp-thread).
template<int C0, int C1, int C2, int MODE>
__global__ void __launch_bounds__(256, 2)
conv3x3_k(const float* __restrict__ xin, const float* __restrict__ bias,
          float* __restrict__ dout, int t)
{
    __shared__ SB sb[2];
    const int tid = threadIdx.x, lx = tid & 31, wq = tid >> 5;
    const int x0 = blockIdx.x * 32, y0 = blockIdx.y * 4;
    const int z  = blockIdx.z;

    const float *p0, *p1, *p2 = nullptr;
    const float4* wsrc;
    float* o0;
    const float* bptr = bias;
    if (MODE == MODE_MSG) {            // inputs: [x0_b, x1_b], out: agg_b
        p0 = xin + (size_t)z * CHW_;            // agent 0, batch z
        p1 = xin + (size_t)(4 + z) * CHW_;      // agent 1, batch z
        wsrc = g_wmsg;
        o0 = g_agg + (size_t)z * CHW_;
    } else if (MODE == MODE_GATES) {   // inputs: [x0_t, agg_t, h]; z=0 -> rh, z=1 -> u
        p0 = xin   + (size_t)t * CHW_;
        p1 = g_agg + (size_t)t * CHW_;
        p2 = g_h;
        wsrc = g_wgates + (size_t)z * (192*144);
        bptr = bias + z * 64;
        o0 = z ? g_u : g_rh;
    } else {                           // CAN: inputs: [x0_t, agg_t, rh]; out: h + dout[t]
        p0 = xin   + (size_t)t * CHW_;
        p1 = g_agg + (size_t)t * CHW_;
        p2 = g_rh;
        wsrc = g_wcan;
        o0 = g_h;
    }

    ull acc[4][4];
    #pragma unroll
    for (int p = 0; p < 4; p++)
        #pragma unroll
        for (int r = 0; r < 4; r++) acc[p][r] = 0ull;

    const int Ct = C0 + C1 + C2;

    auto plane = [&](int ci) -> const float* {
        if (ci < C0) return p0 + (size_t)ci * HW_;
        if (ci < C0 + C1) return p1 + (size_t)(ci - C0) * HW_;
        return p2 + (size_t)(ci - C0 - C1) * HW_;
    };
    // register-staged global load for this thread's staging task of channel ci
    auto gload = [&](int ci) -> float4 {
        if (tid < 60) {
            int rr = tid / 10, q = tid % 10;
            int yy = y0 - 1 + rr, cc = x0 - 4 + 4 * q;
            if ((unsigned)yy < (unsigned)H_ && (unsigned)cc < (unsigned)W_)
                return *(const float4*)(plane(ci) + (size_t)yy * W_ + cc);
            return make_float4(0.f, 0.f, 0.f, 0.f);
        } else if (tid < 204) {
            return wsrc[(size_t)ci * 144 + (tid - 60)];
        }
        return make_float4(0.f, 0.f, 0.f, 0.f);
    };
    auto sstore = [&](SB& b, float4 v) {
        if (tid < 60)       b.in4[tid / 10][tid % 10] = v;
        else if (tid < 204) b.w4[tid - 60] = v;
    };

    // prologue
    sstore(sb[0], gload(0));
    __syncthreads();

    for (int ci = 0; ci < Ct; ci++) {
        float4 nxt;
        const bool more = (ci + 1 < Ct);
        if (more) nxt = gload(ci + 1);         // LDG issued before compute

        const SB& b = sb[ci & 1];
        const float* in = (const float*)b.in4;
        ull iv[6][3];
        #pragma unroll
        for (int rr = 0; rr < 6; rr++)
            #pragma unroll
            for (int dx = 0; dx < 3; dx++) {
                float v = in[rr * 40 + lx + 3 + dx];
                iv[rr][dx] = pk2(v, v);
            }
        const ull* wp = ((const ull*)b.w4) + wq * 36;   // this warp's 4 pairs
        #pragma unroll
        for (int p = 0; p < 4; p++) {
            ull wk[9];
            #pragma unroll
            for (int k = 0; k < 9; k++) wk[k] = wp[p * 9 + k];
            #pragma unroll
            for (int r = 0; r < 4; r++)
                #pragma unroll
                for (int dy = 0; dy < 3; dy++)
                    #pragma unroll
                    for (int dx = 0; dx < 3; dx++)
                        fma2(acc[p][r], wk[dy * 3 + dx], iv[r + dy][dx]);
        }
        if (more) sstore(sb[(ci + 1) & 1], nxt);  // consume LDG after compute
        __syncthreads();
    }

    // ---------------- epilogue ----------------
    const int xg = x0 + lx;
    #pragma unroll
    for (int p = 0; p < 4; p++) {
        int co = wq * 8 + 2 * p;
        float b0 = bptr[co], b1 = bptr[co + 1];
        #pragma unroll
        for (int r = 0; r < 4; r++) {
            float ax, ay;
            asm("mov.b64 {%0,%1},%2;" : "=f"(ax), "=f"(ay) : "l"(acc[p][r]));
            ax += b0; ay += b1;
            size_t off0 = (size_t)co * HW_ + (size_t)(y0 + r) * W_ + xg;
            size_t off1 = off0 + HW_;
            if (MODE == MODE_MSG) {
                o0[off0] = 0.5f * (p0[off0] + ax);
                o0[off1] = 0.5f * (p0[off1] + ay);
            } else if (MODE == MODE_GATES) {
                float s0 = 1.f / (1.f + expf(-ax));
                float s1 = 1.f / (1.f + expf(-ay));
                if (z == 0) { o0[off0] = s0 * g_h[off0]; o0[off1] = s1 * g_h[off1]; }
                else        { o0[off0] = s0;             o0[off1] = s1;             }
            } else {
                float c0 = tanhf(ax), c1 = tanhf(ay);
                float u0 = g_u[off0], u1 = g_u[off1];
                float h0 = g_h[off0], h1 = g_h[off1];
                float n0 = h0 + u0 * (c0 - h0);
                float n1 = h1 + u1 * (c1 - h1);
                g_h[off0] = n0; g_h[off1] = n1;
                float* ot = dout + (size_t)t * CHW_;
                ot[off0] = n0; ot[off1] = n1;
            }
        }
    }
}

// ---------------- weight repack: [co][ci][3][3] -> [ci][pair][tap] float2 ----------------
__global__ void repack_k(const float* __restrict__ mw, const float* __restrict__ gw,
                         const float* __restrict__ cw)
{
    int i = blockIdx.x * blockDim.x + threadIdx.x;
    if (i < 128 * 288) {                       // msg: Cout=64, Cin=128
        int k = i % 9, pr = (i / 9) & 31, ci = i / 288;
        ((float2*)g_wmsg)[i] = make_float2(mw[((2 * pr) * 128 + ci) * 9 + k],
                                           mw[((2 * pr + 1) * 128 + ci) * 9 + k]);
    }
    int j = i - 128 * 288;
    if (j >= 0 && j < 2 * 192 * 288) {         // gates: Cout=128 (2 halves), Cin=192
        int k = j % 9, pr = (j / 9) & 31, ci = (j / 288) % 192, zz = j / (192 * 288);
        int co = zz * 64 + 2 * pr;
        ((float2*)g_wgates)[j] = make_float2(gw[(co * 192 + ci) * 9 + k],
                                             gw[((co + 1) * 192 + ci) * 9 + k]);
    }
    int m = j - 2 * 192 * 288;
    if (m >= 0 && m < 192 * 288) {             // can: Cout=64, Cin=192
        int k = m % 9, pr = (m / 9) & 31, ci = m / 288;
        ((float2*)g_wcan)[m] = make_float2(cw[((2 * pr) * 192 + ci) * 9 + k],
                                           cw[((2 * pr + 1) * 192 + ci) * 9 + k]);
    }
}

__global__ void zero_h_k()
{
    int i = blockIdx.x * blockDim.x + threadIdx.x;
    int st = gridDim.x * blockDim.x;
    for (; i < CHW_; i += st) g_h[i] = 0.f;
}

// ---------------- launch ----------------
extern "C" void kernel_launch(void* const* d_in, const int* in_sizes, int n_in,
                              void* d_out, int out_size)
{
    const float* x  = (const float*)d_in[0];
    const float* mw = (const float*)d_in[1];
    const float* mb = (const float*)d_in[2];
    const float* gw = (const float*)d_in[3];
    const float* gb = (const float*)d_in[4];
    const float* cw = (const float*)d_in[5];
    const float* cb = (const float*)d_in[6];
    float* out = (float*)d_out;

    const int tot = 128 * 288 + 2 * 192 * 288 + 192 * 288;
    repack_k<<<(tot + 255) / 256, 256>>>(mw, gw, cw);
    zero_h_k<<<592, 256>>>();

    // message conv + agg, all 4 batches
    conv3x3_k<64, 64, 0, MODE_MSG><<<dim3(11, 50, 4), 256>>>(x, mb, nullptr, 0);

    // ConvGRU scan over the 4 "sequence" elements
    for (int t = 0; t < 4; t++) {
        conv3x3_k<64, 64, 64, MODE_GATES><<<dim3(11, 50, 2), 256>>>(x, gb, nullptr, t);
        conv3x3_k<64, 64, 64, MODE_CAN  ><<<dim3(11, 50, 1), 256>>>(x, cb, out, t);
    }
}